// round 7
// baseline (speedup 1.0000x reference)
#include <cuda_runtime.h>
#include <cuda_bf16.h>

// VanillaRNN: h_{t+1} = tanh(x_t*Win + h_t@Whh + bh) for 127 steps, out = h@Wout + bout.
// B=2048, T=128, H=512, C=10.
//
// CHAOTIC recurrence (gain ~2.5x/step): must replicate the reference (jax/XLA:CPU,
// fast-math default ON) fp32 arithmetic bit-for-bit:
//  - h@Whh: single-accumulator FMA chain per output, ascending k (Eigen gebp/oneDNN;
//    kc-blocking and threading never split the k-chain)
//  - elementwise (LLVM fast-math contraction): s = fma(x, Win, dot) + bh
//  - tanh: XLA EmitFastTanh with_fma variant — clamp +/-7.99881172180175781,
//    FMA Horner, num = x*p, IEEE division, |x|<0.0004 -> x.

#define BB 2048
#define TT 128
#define HH 512
#define CC 10
#define BT 16
#define NTHREADS 512

// XLA llvm_ir EmitFastTanh(with_fma=true) semantics.
__device__ __forceinline__ float tanh_xla_fma(float a_x) {
    const float kClamp = 7.99881172180175781f;
    float x = fminf(fmaxf(a_x, -kClamp), kClamp);
    float x2 = __fmul_rn(x, x);
    // numerator coeffs alpha_13..alpha_1 (Horner in x2, FMA-contracted)
    float p = fmaf(x2, -2.76076847742355e-16f, 2.00018790482477e-13f);
    p = fmaf(x2, p, -8.60467152213735e-11f);
    p = fmaf(x2, p,  5.12229709037114e-08f);
    p = fmaf(x2, p,  1.48572235717979e-05f);
    p = fmaf(x2, p,  6.37261928875436e-04f);
    p = fmaf(x2, p,  4.89352455891786e-03f);
    p = __fmul_rn(x, p);
    // denominator coeffs beta_6..beta_0
    float q = fmaf(x2, 1.19825839466702e-06f, 1.18534705686654e-04f);
    q = fmaf(x2, q, 2.26843463243900e-03f);
    q = fmaf(x2, q, 4.89352518554385e-03f);
    float r = __fdiv_rn(p, q);
    return (fabsf(a_x) < 0.0004f) ? a_x : r;
}

__global__ __launch_bounds__(NTHREADS, 1)
void vanilla_rnn_kernel(const float* __restrict__ x,     // [B, T]
                        const float* __restrict__ Win,   // [1, H]
                        const float* __restrict__ Whh,   // [H, H]
                        const float* __restrict__ bh,    // [H]
                        const float* __restrict__ Wout,  // [H, C]
                        const float* __restrict__ bout,  // [C]
                        float* __restrict__ out)         // [B, C]
{
    __shared__ float h_s[HH][BT];   // h_s[k][b] = h[b0+b][k]   (32 KB)
    __shared__ float xs[BT];

    const int tid = threadIdx.x;
    const int j   = tid;            // hidden column owned by this thread
    const int b0  = blockIdx.x * BT;

    for (int i = tid; i < HH * BT; i += NTHREADS)
        (&h_s[0][0])[i] = 0.0f;

    const float win_j = Win[j];
    const float bh_j  = bh[j];

    __syncthreads();

    for (int t = 0; t < TT - 1; ++t) {
        if (tid < BT) xs[tid] = x[(b0 + tid) * TT + t];
        __syncthreads();   // xs visible; orders previous step's h writes before reads

        // dot: acc[b] = sum_k h[b][k]*Whh[k][j], single FMA chain, ascending k
        float acc[BT];
        #pragma unroll
        for (int b = 0; b < BT; ++b) acc[b] = 0.0f;

        #pragma unroll 8
        for (int k = 0; k < HH; ++k) {
            const float w = Whh[k * HH + j];              // coalesced, L2-resident
            const float4* hp = reinterpret_cast<const float4*>(&h_s[k][0]);
            #pragma unroll
            for (int q = 0; q < BT / 4; ++q) {
                float4 hv = hp[q];                        // broadcast LDS.128
                acc[4 * q + 0] = fmaf(hv.x, w, acc[4 * q + 0]);
                acc[4 * q + 1] = fmaf(hv.y, w, acc[4 * q + 1]);
                acc[4 * q + 2] = fmaf(hv.z, w, acc[4 * q + 2]);
                acc[4 * q + 3] = fmaf(hv.w, w, acc[4 * q + 3]);
            }
        }

        __syncthreads();   // all reads of h done before overwrite

        #pragma unroll
        for (int b = 0; b < BT; ++b) {
            // fast-math contraction: fma(x, Win, dot), then + bh
            float s = fmaf(xs[b], win_j, acc[b]);
            s = __fadd_rn(s, bh_j);
            h_s[j][b] = tanh_xla_fma(s);
        }
    }
    __syncthreads();

    // out[b][c] = (sum_j h[b][j]*Wout[j][c]) + bout[c], chain ascending j
    if (tid < BT * CC) {
        const int b = tid / CC;
        const int c = tid % CC;
        float s = 0.0f;
        #pragma unroll 8
        for (int jj = 0; jj < HH; ++jj)
            s = fmaf(h_s[jj][b], Wout[jj * CC + c], s);
        out[(b0 + b) * CC + c] = __fadd_rn(s, bout[c]);
    }
}

extern "C" void kernel_launch(void* const* d_in, const int* in_sizes, int n_in,
                              void* d_out, int out_size)
{
    // Expected (setup_inputs dict order): x[262144], Win[512], Whh[262144],
    // bh[512], Wout[5120], bout[10]. Defensive remap if alphabetical order.
    int ix = 0, iwin = 1, iwhh = 2, ibh = 3, iwout = 4, ibout = 5;
    if (n_in == 6 && in_sizes[2] == 5120) {
        // alphabetical: Whh, Win, Wout, bh, bout, x
        iwhh = 0; iwin = 1; iwout = 2; ibh = 3; ibout = 4; ix = 5;
    }

    const float* x    = (const float*)d_in[ix];
    const float* Win  = (const float*)d_in[iwin];
    const float* Whh  = (const float*)d_in[iwhh];
    const float* bh   = (const float*)d_in[ibh];
    const float* Wout = (const float*)d_in[iwout];
    const float* bout = (const float*)d_in[ibout];
    float* out = (float*)d_out;

    dim3 grid(BB / BT);      // 128 CTAs
    dim3 block(NTHREADS);    // 512 threads
    vanilla_rnn_kernel<<<grid, block>>>(x, Win, Whh, bh, Wout, bout, out);
}

// round 10
// speedup vs baseline: 1.2838x; 1.2838x over previous
#include <cuda_runtime.h>
#include <cuda_bf16.h>

// VanillaRNN: h_{t+1} = tanh(fma(x_t,Win, h_t@Whh) + bh), 127 steps; out = h@Wout + bout.
// B=2048, T=128, H=512, C=10.
//
// BIT-EXACT arithmetic (verified rel_err == 0.0, do not change):
//  - h@Whh: single-accumulator IEEE-RN FMA chain per (b,j), ascending k
//  - elementwise: s = fma(x, Win, dot) + bh  (contracted, then one rounded add)
//  - tanh: XLA EmitFastTanh with_fma: clamp +/-7.99881172180175781, FMA Horner,
//    num = x*p, IEEE div, |x|<0.0004 -> x
//
// Perf structure (R2): fma.rn.f32x2 packed FMA (2 independent IEEE lanes ->
// bitwise identical to scalar chains) + 2 hidden columns per thread so each
// h-broadcast LDS.128 feeds twice as many FMAs. 256 thr/CTA, 128 CTAs.

#define BB 2048
#define TT 128
#define HH 512
#define CC 10
#define BT 16
#define NTHREADS 256

typedef unsigned long long ull;

__device__ __forceinline__ void fma2(ull& acc, ull h2, ull w2) {
    // two independent fp32 RN FMAs: acc.lo = fma(h.lo, w.lo, acc.lo), same .hi
    asm("fma.rn.f32x2 %0, %1, %2, %0;" : "+l"(acc) : "l"(h2), "l"(w2));
}
__device__ __forceinline__ ull dup2(float w) {
    ull r; asm("mov.b64 %0, {%1, %1};" : "=l"(r) : "f"(w)); return r;
}
__device__ __forceinline__ void unpack2(float& lo, float& hi, ull v) {
    asm("mov.b64 {%0, %1}, %2;" : "=f"(lo), "=f"(hi) : "l"(v));
}

// XLA llvm_ir EmitFastTanh(with_fma=true) — exact semantics (frozen).
__device__ __forceinline__ float tanh_xla_fma(float a_x) {
    const float kClamp = 7.99881172180175781f;
    float x = fminf(fmaxf(a_x, -kClamp), kClamp);
    float x2 = __fmul_rn(x, x);
    float p = fmaf(x2, -2.76076847742355e-16f, 2.00018790482477e-13f);
    p = fmaf(x2, p, -8.60467152213735e-11f);
    p = fmaf(x2, p,  5.12229709037114e-08f);
    p = fmaf(x2, p,  1.48572235717979e-05f);
    p = fmaf(x2, p,  6.37261928875436e-04f);
    p = fmaf(x2, p,  4.89352455891786e-03f);
    p = __fmul_rn(x, p);
    float q = fmaf(x2, 1.19825839466702e-06f, 1.18534705686654e-04f);
    q = fmaf(x2, q, 2.26843463243900e-03f);
    q = fmaf(x2, q, 4.89352518554385e-03f);
    float r = __fdiv_rn(p, q);
    return (fabsf(a_x) < 0.0004f) ? a_x : r;
}

__global__ __launch_bounds__(NTHREADS, 1)
void vanilla_rnn_kernel(const float* __restrict__ x,     // [B, T]
                        const float* __restrict__ Win,   // [1, H]
                        const float* __restrict__ Whh,   // [H, H]
                        const float* __restrict__ bh,    // [H]
                        const float* __restrict__ Wout,  // [H, C]
                        const float* __restrict__ bout,  // [C]
                        float* __restrict__ out)         // [B, C]
{
    __shared__ float h_s[HH][BT];   // h_s[k][b] (32 KB, rows 64B-aligned)
    __shared__ float xs[BT];

    const int tid = threadIdx.x;
    const int j0  = tid;            // this thread owns hidden columns j0, j1
    const int j1  = tid + 256;
    const int b0  = blockIdx.x * BT;

    for (int i = tid; i < HH * BT; i += NTHREADS)
        (&h_s[0][0])[i] = 0.0f;

    const float win_j0 = Win[j0], bh_j0 = bh[j0];
    const float win_j1 = Win[j1], bh_j1 = bh[j1];

    __syncthreads();

    for (int t = 0; t < TT - 1; ++t) {
        if (tid < BT) xs[tid] = x[(b0 + tid) * TT + t];
        __syncthreads();   // xs visible; previous h writes ordered before reads

        // acc{0,1}[i] holds packed (b=2i, b=2i+1) chains for columns j0, j1.
        ull acc0[BT / 2], acc1[BT / 2];
        #pragma unroll
        for (int i = 0; i < BT / 2; ++i) { acc0[i] = 0ull; acc1[i] = 0ull; }

        #pragma unroll 8
        for (int k = 0; k < HH; ++k) {
            const float w0 = Whh[k * HH + j0];            // coalesced, L2-resident
            const float w1 = Whh[k * HH + j1];
            const ull wp0 = dup2(w0);
            const ull wp1 = dup2(w1);
            const ulonglong2* hp = reinterpret_cast<const ulonglong2*>(&h_s[k][0]);
            #pragma unroll
            for (int q = 0; q < 4; ++q) {                 // 4x LDS.128 broadcast
                ulonglong2 hv = hp[q];                    // (b=4q..4q+3) as 2 pairs
                fma2(acc0[2 * q + 0], hv.x, wp0);
                fma2(acc0[2 * q + 1], hv.y, wp0);
                fma2(acc1[2 * q + 0], hv.x, wp1);
                fma2(acc1[2 * q + 1], hv.y, wp1);
            }
        }

        __syncthreads();   // all h reads done before overwrite

        // epilogue: bit-exact elementwise per (b, j); vectorized STS.128 writes
        {
            float4 hv[BT / 4];
            #pragma unroll
            for (int i = 0; i < BT / 2; ++i) {
                float alo, ahi; unpack2(alo, ahi, acc0[i]);
                float s0 = __fadd_rn(fmaf(xs[2 * i + 0], win_j0, alo), bh_j0);
                float s1 = __fadd_rn(fmaf(xs[2 * i + 1], win_j0, ahi), bh_j0);
                ((float*)hv)[2 * i + 0] = tanh_xla_fma(s0);
                ((float*)hv)[2 * i + 1] = tanh_xla_fma(s1);
            }
            float4* dst = reinterpret_cast<float4*>(&h_s[j0][0]);
            #pragma unroll
            for (int q = 0; q < BT / 4; ++q) dst[q] = hv[q];

            #pragma unroll
            for (int i = 0; i < BT / 2; ++i) {
                float alo, ahi; unpack2(alo, ahi, acc1[i]);
                float s0 = __fadd_rn(fmaf(xs[2 * i + 0], win_j1, alo), bh_j1);
                float s1 = __fadd_rn(fmaf(xs[2 * i + 1], win_j1, ahi), bh_j1);
                ((float*)hv)[2 * i + 0] = tanh_xla_fma(s0);
                ((float*)hv)[2 * i + 1] = tanh_xla_fma(s1);
            }
            dst = reinterpret_cast<float4*>(&h_s[j1][0]);
            #pragma unroll
            for (int q = 0; q < BT / 4; ++q) dst[q] = hv[q];
        }
    }
    __syncthreads();

    // out[b][c] = (sum_j h[b][j]*Wout[j][c]) + bout[c], chain ascending j (frozen)
    if (tid < BT * CC) {
        const int b = tid / CC;
        const int c = tid % CC;
        float s = 0.0f;
        #pragma unroll 8
        for (int jj = 0; jj < HH; ++jj)
            s = fmaf(h_s[jj][b], Wout[jj * CC + c], s);
        out[(b0 + b) * CC + c] = __fadd_rn(s, bout[c]);
    }
}

extern "C" void kernel_launch(void* const* d_in, const int* in_sizes, int n_in,
                              void* d_out, int out_size)
{
    // dict order: x, Win, Whh, bh, Wout, bout; defensive remap if alphabetical.
    int ix = 0, iwin = 1, iwhh = 2, ibh = 3, iwout = 4, ibout = 5;
    if (n_in == 6 && in_sizes[2] == 5120) {
        iwhh = 0; iwin = 1; iwout = 2; ibh = 3; ibout = 4; ix = 5;
    }

    const float* x    = (const float*)d_in[ix];
    const float* Win  = (const float*)d_in[iwin];
    const float* Whh  = (const float*)d_in[iwhh];
    const float* bh   = (const float*)d_in[ibh];
    const float* Wout = (const float*)d_in[iwout];
    const float* bout = (const float*)d_in[ibout];
    float* out = (float*)d_out;

    dim3 grid(BB / BT);      // 128 CTAs
    dim3 block(NTHREADS);    // 256 threads, 2 hidden columns each
    vanilla_rnn_kernel<<<grid, block>>>(x, Win, Whh, bh, Wout, bout, out);
}

// round 13
// speedup vs baseline: 1.3195x; 1.0278x over previous
#include <cuda_runtime.h>
#include <cuda_bf16.h>

// VanillaRNN: h_{t+1} = tanh(fma(x_t,Win, h_t@Whh) + bh), 127 steps; out = h@Wout + bout.
// B=2048, T=128, H=512, C=10.
//
// BIT-EXACT arithmetic (verified rel_err == 0.0 twice, FROZEN):
//  - h@Whh: single-accumulator IEEE-RN FMA chain per (b,j), ascending k
//  - elementwise: s = fma(x, Win, dot) + bh
//  - tanh: XLA EmitFastTanh with_fma: clamp +/-7.99881172180175781, FMA Horner,
//    num = x*p, IEEE div, |x|<0.0004 -> x
//
// Perf structure (R3): same FFMA2 + 2-columns-per-thread shape as R9, but
// 2 CTAs/SM (grid 256, BT=8) to restore 4 warps/SMSP of latency hiding
// (R9 measured issue=39% at 2 warps/SMSP -> L2-latency-bound), and ADJACENT
// columns per thread (j=2*tid, 2*tid+1) so weights load as one LDG.64.

#define BB 2048
#define TT 128
#define HH 512
#define CC 10
#define BT 8
#define NTHREADS 256

typedef unsigned long long ull;

__device__ __forceinline__ void fma2(ull& acc, ull h2, ull w2) {
    // two independent fp32 RN FMAs (lanewise identical to scalar fmaf chains)
    asm("fma.rn.f32x2 %0, %1, %2, %0;" : "+l"(acc) : "l"(h2), "l"(w2));
}
__device__ __forceinline__ ull dup2(float w) {
    ull r; asm("mov.b64 %0, {%1, %1};" : "=l"(r) : "f"(w)); return r;
}
__device__ __forceinline__ void unpack2(float& lo, float& hi, ull v) {
    asm("mov.b64 {%0, %1}, %2;" : "=f"(lo), "=f"(hi) : "l"(v));
}

// XLA llvm_ir EmitFastTanh(with_fma=true) — exact semantics (frozen).
__device__ __forceinline__ float tanh_xla_fma(float a_x) {
    const float kClamp = 7.99881172180175781f;
    float x = fminf(fmaxf(a_x, -kClamp), kClamp);
    float x2 = __fmul_rn(x, x);
    float p = fmaf(x2, -2.76076847742355e-16f, 2.00018790482477e-13f);
    p = fmaf(x2, p, -8.60467152213735e-11f);
    p = fmaf(x2, p,  5.12229709037114e-08f);
    p = fmaf(x2, p,  1.48572235717979e-05f);
    p = fmaf(x2, p,  6.37261928875436e-04f);
    p = fmaf(x2, p,  4.89352455891786e-03f);
    p = __fmul_rn(x, p);
    float q = fmaf(x2, 1.19825839466702e-06f, 1.18534705686654e-04f);
    q = fmaf(x2, q, 2.26843463243900e-03f);
    q = fmaf(x2, q, 4.89352518554385e-03f);
    float r = __fdiv_rn(p, q);
    return (fabsf(a_x) < 0.0004f) ? a_x : r;
}

__global__ __launch_bounds__(NTHREADS, 2)
void vanilla_rnn_kernel(const float* __restrict__ x,     // [B, T]
                        const float* __restrict__ Win,   // [1, H]
                        const float* __restrict__ Whh,   // [H, H]
                        const float* __restrict__ bh,    // [H]
                        const float* __restrict__ Wout,  // [H, C]
                        const float* __restrict__ bout,  // [C]
                        float* __restrict__ out)         // [B, C]
{
    __shared__ float h_s[HH][BT];   // h_s[k][b] (16 KB; rows 32B)
    __shared__ float xs[BT];

    const int tid = threadIdx.x;
    const int j0  = 2 * tid;        // adjacent hidden columns per thread
    const int j1  = 2 * tid + 1;
    const int b0  = blockIdx.x * BT;

    for (int i = tid; i < HH * BT; i += NTHREADS)
        (&h_s[0][0])[i] = 0.0f;

    const float win_j0 = Win[j0], bh_j0 = bh[j0];
    const float win_j1 = Win[j1], bh_j1 = bh[j1];

    __syncthreads();

    for (int t = 0; t < TT - 1; ++t) {
        if (tid < BT) xs[tid] = x[(b0 + tid) * TT + t];
        __syncthreads();   // xs visible; previous h writes ordered before reads

        // acc{0,1}[i]: packed (b=2i, b=2i+1) chains for columns j0, j1
        ull acc0[BT / 2], acc1[BT / 2];
        #pragma unroll
        for (int i = 0; i < BT / 2; ++i) { acc0[i] = 0ull; acc1[i] = 0ull; }

        #pragma unroll 8
        for (int k = 0; k < HH; ++k) {
            // one LDG.64: Whh[k][2*tid], Whh[k][2*tid+1] (256B/warp, coalesced)
            const float2 wv = reinterpret_cast<const float2*>(Whh + k * HH)[tid];
            const ull wp0 = dup2(wv.x);
            const ull wp1 = dup2(wv.y);
            const ulonglong2* hp = reinterpret_cast<const ulonglong2*>(&h_s[k][0]);
            ulonglong2 hv0 = hp[0];                       // b=0..3 (2 pairs)
            ulonglong2 hv1 = hp[1];                       // b=4..7
            fma2(acc0[0], hv0.x, wp0);
            fma2(acc0[1], hv0.y, wp0);
            fma2(acc0[2], hv1.x, wp0);
            fma2(acc0[3], hv1.y, wp0);
            fma2(acc1[0], hv0.x, wp1);
            fma2(acc1[1], hv0.y, wp1);
            fma2(acc1[2], hv1.x, wp1);
            fma2(acc1[3], hv1.y, wp1);
        }

        __syncthreads();   // all h reads done before overwrite

        // epilogue: bit-exact elementwise; vectorized STS.128 writes
        {
            float hv[BT];
            #pragma unroll
            for (int i = 0; i < BT / 2; ++i) {
                float alo, ahi; unpack2(alo, ahi, acc0[i]);
                float s0 = __fadd_rn(fmaf(xs[2 * i + 0], win_j0, alo), bh_j0);
                float s1 = __fadd_rn(fmaf(xs[2 * i + 1], win_j0, ahi), bh_j0);
                hv[2 * i + 0] = tanh_xla_fma(s0);
                hv[2 * i + 1] = tanh_xla_fma(s1);
            }
            float4* dst0 = reinterpret_cast<float4*>(&h_s[j0][0]);
            dst0[0] = make_float4(hv[0], hv[1], hv[2], hv[3]);
            dst0[1] = make_float4(hv[4], hv[5], hv[6], hv[7]);

            #pragma unroll
            for (int i = 0; i < BT / 2; ++i) {
                float alo, ahi; unpack2(alo, ahi, acc1[i]);
                float s0 = __fadd_rn(fmaf(xs[2 * i + 0], win_j1, alo), bh_j1);
                float s1 = __fadd_rn(fmaf(xs[2 * i + 1], win_j1, ahi), bh_j1);
                hv[2 * i + 0] = tanh_xla_fma(s0);
                hv[2 * i + 1] = tanh_xla_fma(s1);
            }
            float4* dst1 = reinterpret_cast<float4*>(&h_s[j1][0]);
            dst1[0] = make_float4(hv[0], hv[1], hv[2], hv[3]);
            dst1[1] = make_float4(hv[4], hv[5], hv[6], hv[7]);
        }
    }
    __syncthreads();

    // out[b][c] = (sum_j h[b][j]*Wout[j][c]) + bout[c], chain ascending j (frozen)
    if (tid < BT * CC) {
        const int b = tid / CC;
        const int c = tid % CC;
        float s = 0.0f;
        #pragma unroll 8
        for (int jj = 0; jj < HH; ++jj)
            s = fmaf(h_s[jj][b], Wout[jj * CC + c], s);
        out[(b0 + b) * CC + c] = __fadd_rn(s, bout[c]);
    }
}

extern "C" void kernel_launch(void* const* d_in, const int* in_sizes, int n_in,
                              void* d_out, int out_size)
{
    // dict order: x, Win, Whh, bh, Wout, bout; defensive remap if alphabetical.
    int ix = 0, iwin = 1, iwhh = 2, ibh = 3, iwout = 4, ibout = 5;
    if (n_in == 6 && in_sizes[2] == 5120) {
        iwhh = 0; iwin = 1; iwout = 2; ibh = 3; ibout = 4; ix = 5;
    }

    const float* x    = (const float*)d_in[ix];
    const float* Win  = (const float*)d_in[iwin];
    const float* Whh  = (const float*)d_in[iwhh];
    const float* bh   = (const float*)d_in[ibh];
    const float* Wout = (const float*)d_in[iwout];
    const float* bout = (const float*)d_in[ibout];
    float* out = (float*)d_out;

    dim3 grid(BB / BT);      // 256 CTAs -> 2 CTAs/SM on most SMs
    dim3 block(NTHREADS);    // 256 threads, 2 adjacent hidden columns each
    vanilla_rnn_kernel<<<grid, block>>>(x, Win, Whh, bh, Wout, bout, out);
}

// round 14
// speedup vs baseline: 1.5339x; 1.1625x over previous
#include <cuda_runtime.h>
#include <cuda_bf16.h>

// VanillaRNN: h_{t+1} = tanh(fma(x_t,Win, h_t@Whh) + bh), 127 steps; out = h@Wout + bout.
// B=2048, T=128, H=512, C=10.
//
// BIT-EXACT arithmetic (verified rel_err == 0.0 three times, FROZEN):
//  - h@Whh: single-accumulator IEEE-RN FMA chain per (b,j), ascending k
//  - elementwise: s = fma(x, Win, dot) + bh
//  - tanh: XLA EmitFastTanh with_fma: clamp +/-7.99881172180175781, FMA Horner,
//    num = x*p, IEEE div, |x|<0.0004 -> x
//
// Perf structure (R4): R12 shape (FFMA2, 2 adjacent cols/thread, 2 CTAs/SM)
// + distance-1 double-buffered REGISTER prefetch of the next 8 k-rows of
// Whh. Block wall (>=512 cyc FFMA2 floor per SMSP) >> L2 latency (262) so
// one block of lookahead fully hides the weight loads that capped issue at 40%.

#define BB 2048
#define TT 128
#define HH 512
#define CC 10
#define BT 8
#define NTHREADS 256

typedef unsigned long long ull;

__device__ __forceinline__ void fma2(ull& acc, ull h2, ull w2) {
    // two independent fp32 RN FMAs (lanewise identical to scalar fmaf chains)
    asm("fma.rn.f32x2 %0, %1, %2, %0;" : "+l"(acc) : "l"(h2), "l"(w2));
}
__device__ __forceinline__ ull dup2(float w) {
    ull r; asm("mov.b64 %0, {%1, %1};" : "=l"(r) : "f"(w)); return r;
}
__device__ __forceinline__ void unpack2(float& lo, float& hi, ull v) {
    asm("mov.b64 {%0, %1}, %2;" : "=f"(lo), "=f"(hi) : "l"(v));
}

// XLA llvm_ir EmitFastTanh(with_fma=true) — exact semantics (frozen).
__device__ __forceinline__ float tanh_xla_fma(float a_x) {
    const float kClamp = 7.99881172180175781f;
    float x = fminf(fmaxf(a_x, -kClamp), kClamp);
    float x2 = __fmul_rn(x, x);
    float p = fmaf(x2, -2.76076847742355e-16f, 2.00018790482477e-13f);
    p = fmaf(x2, p, -8.60467152213735e-11f);
    p = fmaf(x2, p,  5.12229709037114e-08f);
    p = fmaf(x2, p,  1.48572235717979e-05f);
    p = fmaf(x2, p,  6.37261928875436e-04f);
    p = fmaf(x2, p,  4.89352455891786e-03f);
    p = __fmul_rn(x, p);
    float q = fmaf(x2, 1.19825839466702e-06f, 1.18534705686654e-04f);
    q = fmaf(x2, q, 2.26843463243900e-03f);
    q = fmaf(x2, q, 4.89352518554385e-03f);
    float r = __fdiv_rn(p, q);
    return (fabsf(a_x) < 0.0004f) ? a_x : r;
}

// one unroll-8 compute block: k = blk*8 .. blk*8+7, weights from wb[8]
__device__ __forceinline__ void compute_block(
    const float2 wb[8], const float (*h_s)[BT], int blk,
    ull acc0[BT / 2], ull acc1[BT / 2])
{
    #pragma unroll
    for (int i = 0; i < 8; ++i) {
        const int k = blk * 8 + i;
        const ull wp0 = dup2(wb[i].x);
        const ull wp1 = dup2(wb[i].y);
        const ulonglong2* hp = reinterpret_cast<const ulonglong2*>(&h_s[k][0]);
        ulonglong2 hv0 = hp[0];                  // b=0..3 (2 packed pairs)
        ulonglong2 hv1 = hp[1];                  // b=4..7
        fma2(acc0[0], hv0.x, wp0);
        fma2(acc0[1], hv0.y, wp0);
        fma2(acc0[2], hv1.x, wp0);
        fma2(acc0[3], hv1.y, wp0);
        fma2(acc1[0], hv0.x, wp1);
        fma2(acc1[1], hv0.y, wp1);
        fma2(acc1[2], hv1.x, wp1);
        fma2(acc1[3], hv1.y, wp1);
    }
}

__global__ __launch_bounds__(NTHREADS, 2)
void vanilla_rnn_kernel(const float* __restrict__ x,     // [B, T]
                        const float* __restrict__ Win,   // [1, H]
                        const float* __restrict__ Whh,   // [H, H]
                        const float* __restrict__ bh,    // [H]
                        const float* __restrict__ Wout,  // [H, C]
                        const float* __restrict__ bout,  // [C]
                        float* __restrict__ out)         // [B, C]
{
    __shared__ float h_s[HH][BT];   // h_s[k][b] (16 KB)
    __shared__ float xs[BT];

    const int tid = threadIdx.x;
    const int j0  = 2 * tid;        // adjacent hidden columns per thread
    const int j1  = 2 * tid + 1;
    const int b0  = blockIdx.x * BT;

    for (int i = tid; i < HH * BT; i += NTHREADS)
        (&h_s[0][0])[i] = 0.0f;

    const float win_j0 = Win[j0], bh_j0 = bh[j0];
    const float win_j1 = Win[j1], bh_j1 = bh[j1];

    // Whh viewed as [512 rows][256 float2]; this thread reads column pair tid.
    const float2* W2 = reinterpret_cast<const float2*>(Whh);

    __syncthreads();

    for (int t = 0; t < TT - 1; ++t) {
        if (tid < BT) xs[tid] = x[(b0 + tid) * TT + t];
        __syncthreads();   // xs visible; previous h writes ordered before reads

        ull acc0[BT / 2], acc1[BT / 2];
        #pragma unroll
        for (int i = 0; i < BT / 2; ++i) { acc0[i] = 0ull; acc1[i] = 0ull; }

        // software pipeline over 64 blocks of 8 k-rows, double-buffered weights
        float2 wbA[8], wbB[8];
        #pragma unroll
        for (int i = 0; i < 8; ++i) wbA[i] = W2[i * (HH / 2) + tid];   // blk 0

        #pragma unroll 1
        for (int blk = 0; blk < 64; blk += 2) {
            // prefetch blk+1 into B, compute blk from A
            const int nb1 = blk + 1;                       // <= 63, in range
            #pragma unroll
            for (int i = 0; i < 8; ++i) wbB[i] = W2[(nb1 * 8 + i) * (HH / 2) + tid];
            compute_block(wbA, h_s, blk, acc0, acc1);

            // prefetch blk+2 into A (wrap last: harmless L2-hit re-read), compute blk+1 from B
            const int nb2 = (blk + 2) & 63;
            #pragma unroll
            for (int i = 0; i < 8; ++i) wbA[i] = W2[(nb2 * 8 + i) * (HH / 2) + tid];
            compute_block(wbB, h_s, blk + 1, acc0, acc1);
        }

        __syncthreads();   // all h reads done before overwrite

        // epilogue: bit-exact elementwise; vectorized STS.128 writes
        {
            float hv[BT];
            #pragma unroll
            for (int i = 0; i < BT / 2; ++i) {
                float alo, ahi; unpack2(alo, ahi, acc0[i]);
                float s0 = __fadd_rn(fmaf(xs[2 * i + 0], win_j0, alo), bh_j0);
                float s1 = __fadd_rn(fmaf(xs[2 * i + 1], win_j0, ahi), bh_j0);
                hv[2 * i + 0] = tanh_xla_fma(s0);
                hv[2 * i + 1] = tanh_xla_fma(s1);
            }
            float4* dst0 = reinterpret_cast<float4*>(&h_s[j0][0]);
            dst0[0] = make_float4(hv[0], hv[1], hv[2], hv[3]);
            dst0[1] = make_float4(hv[4], hv[5], hv[6], hv[7]);

            #pragma unroll
            for (int i = 0; i < BT / 2; ++i) {
                float alo, ahi; unpack2(alo, ahi, acc1[i]);
                float s0 = __fadd_rn(fmaf(xs[2 * i + 0], win_j1, alo), bh_j1);
                float s1 = __fadd_rn(fmaf(xs[2 * i + 1], win_j1, ahi), bh_j1);
                hv[2 * i + 0] = tanh_xla_fma(s0);
                hv[2 * i + 1] = tanh_xla_fma(s1);
            }
            float4* dst1 = reinterpret_cast<float4*>(&h_s[j1][0]);
            dst1[0] = make_float4(hv[0], hv[1], hv[2], hv[3]);
            dst1[1] = make_float4(hv[4], hv[5], hv[6], hv[7]);
        }
    }
    __syncthreads();

    // out[b][c] = (sum_j h[b][j]*Wout[j][c]) + bout[c], chain ascending j (frozen)
    if (tid < BT * CC) {
        const int b = tid / CC;
        const int c = tid % CC;
        float s = 0.0f;
        #pragma unroll 8
        for (int jj = 0; jj < HH; ++jj)
            s = fmaf(h_s[jj][b], Wout[jj * CC + c], s);
        out[(b0 + b) * CC + c] = __fadd_rn(s, bout[c]);
    }
}

extern "C" void kernel_launch(void* const* d_in, const int* in_sizes, int n_in,
                              void* d_out, int out_size)
{
    // dict order: x, Win, Whh, bh, Wout, bout; defensive remap if alphabetical.
    int ix = 0, iwin = 1, iwhh = 2, ibh = 3, iwout = 4, ibout = 5;
    if (n_in == 6 && in_sizes[2] == 5120) {
        iwhh = 0; iwin = 1; iwout = 2; ibh = 3; ibout = 4; ix = 5;
    }

    const float* x    = (const float*)d_in[ix];
    const float* Win  = (const float*)d_in[iwin];
    const float* Whh  = (const float*)d_in[iwhh];
    const float* bh   = (const float*)d_in[ibh];
    const float* Wout = (const float*)d_in[iwout];
    const float* bout = (const float*)d_in[ibout];
    float* out = (float*)d_out;

    dim3 grid(BB / BT);      // 256 CTAs -> 2 CTAs/SM on most SMs
    dim3 block(NTHREADS);    // 256 threads, 2 adjacent hidden columns each
    vanilla_rnn_kernel<<<grid, block>>>(x, Win, Whh, bh, Wout, bout, out);
}

// round 15
// speedup vs baseline: 1.6888x; 1.1010x over previous
#include <cuda_runtime.h>
#include <cuda_bf16.h>

// VanillaRNN: h_{t+1} = tanh(fma(x_t,Win, h_t@Whh) + bh), 127 steps; out = h@Wout + bout.
// B=2048, T=128, H=512, C=10.
//
// BIT-EXACT arithmetic (rel_err == 0.0 four times, FROZEN):
//  - h@Whh: single-accumulator IEEE-RN FMA chain per (b,j), ascending k
//  - elementwise: s = fma(x, Win, dot) + bh
//  - tanh: XLA EmitFastTanh with_fma: clamp +/-7.99881172180175781, FMA Horner,
//    num = x*p, IEEE div, |x|<0.0004 -> x
//
// Perf structure (R5): ONE CTA per SM (grid 128, 256 thr, BT=16). Halves both
// the per-SM Whh L2 traffic and L1 wavefronts vs the 2-CTA/SM R13 shape
// (48 wf/k < 64-cyc FFMA2 floor), keeps the same FFMA2 floor, doubles
// per-warp ILP (16 indep fma2 chains/k) to cover latency at 2 warps/SMSP.
// Register weight prefetch (dist-1 double buffer) retained. x pre-staged
// transposed in smem to remove the per-step LDG/barrier dependency.

#define BB 2048
#define TT 128
#define HH 512
#define CC 10
#define BT 16
#define NTHREADS 256

typedef unsigned long long ull;

__device__ __forceinline__ void fma2(ull& acc, ull h2, ull w2) {
    // two independent fp32 RN FMAs (lanewise identical to scalar fmaf chains)
    asm("fma.rn.f32x2 %0, %1, %2, %0;" : "+l"(acc) : "l"(h2), "l"(w2));
}
__device__ __forceinline__ ull dup2(float w) {
    ull r; asm("mov.b64 %0, {%1, %1};" : "=l"(r) : "f"(w)); return r;
}
__device__ __forceinline__ void unpack2(float& lo, float& hi, ull v) {
    asm("mov.b64 {%0, %1}, %2;" : "=f"(lo), "=f"(hi) : "l"(v));
}

// XLA llvm_ir EmitFastTanh(with_fma=true) — exact semantics (frozen).
__device__ __forceinline__ float tanh_xla_fma(float a_x) {
    const float kClamp = 7.99881172180175781f;
    float x = fminf(fmaxf(a_x, -kClamp), kClamp);
    float x2 = __fmul_rn(x, x);
    float p = fmaf(x2, -2.76076847742355e-16f, 2.00018790482477e-13f);
    p = fmaf(x2, p, -8.60467152213735e-11f);
    p = fmaf(x2, p,  5.12229709037114e-08f);
    p = fmaf(x2, p,  1.48572235717979e-05f);
    p = fmaf(x2, p,  6.37261928875436e-04f);
    p = fmaf(x2, p,  4.89352455891786e-03f);
    p = __fmul_rn(x, p);
    float q = fmaf(x2, 1.19825839466702e-06f, 1.18534705686654e-04f);
    q = fmaf(x2, q, 2.26843463243900e-03f);
    q = fmaf(x2, q, 4.89352518554385e-03f);
    float r = __fdiv_rn(p, q);
    return (fabsf(a_x) < 0.0004f) ? a_x : r;
}

// one unroll-8 compute block: k = blk*8 .. blk*8+7, weights from wb[8]
__device__ __forceinline__ void compute_block(
    const float2 wb[8], const float (*h_s)[BT], int blk,
    ull acc0[BT / 2], ull acc1[BT / 2])
{
    #pragma unroll
    for (int i = 0; i < 8; ++i) {
        const int k = blk * 8 + i;
        const ull wp0 = dup2(wb[i].x);
        const ull wp1 = dup2(wb[i].y);
        const ulonglong2* hp = reinterpret_cast<const ulonglong2*>(&h_s[k][0]);
        ulonglong2 h0 = hp[0];                   // b = 0..3  (2 packed pairs)
        ulonglong2 h1 = hp[1];                   // b = 4..7
        ulonglong2 h2 = hp[2];                   // b = 8..11
        ulonglong2 h3 = hp[3];                   // b = 12..15
        fma2(acc0[0], h0.x, wp0);  fma2(acc0[1], h0.y, wp0);
        fma2(acc0[2], h1.x, wp0);  fma2(acc0[3], h1.y, wp0);
        fma2(acc0[4], h2.x, wp0);  fma2(acc0[5], h2.y, wp0);
        fma2(acc0[6], h3.x, wp0);  fma2(acc0[7], h3.y, wp0);
        fma2(acc1[0], h0.x, wp1);  fma2(acc1[1], h0.y, wp1);
        fma2(acc1[2], h1.x, wp1);  fma2(acc1[3], h1.y, wp1);
        fma2(acc1[4], h2.x, wp1);  fma2(acc1[5], h2.y, wp1);
        fma2(acc1[6], h3.x, wp1);  fma2(acc1[7], h3.y, wp1);
    }
}

__global__ __launch_bounds__(NTHREADS, 1)
void vanilla_rnn_kernel(const float* __restrict__ x,     // [B, T]
                        const float* __restrict__ Win,   // [1, H]
                        const float* __restrict__ Whh,   // [H, H]
                        const float* __restrict__ bh,    // [H]
                        const float* __restrict__ Wout,  // [H, C]
                        const float* __restrict__ bout,  // [C]
                        float* __restrict__ out)         // [B, C]
{
    __shared__ float h_s[HH][BT];        // h_s[k][b]        (32 KB)
    __shared__ float xs_all[TT][BT];     // xs_all[t][b]     (8 KB)

    const int tid = threadIdx.x;
    const int j0  = 2 * tid;             // adjacent hidden columns per thread
    const int j1  = 2 * tid + 1;
    const int b0  = blockIdx.x * BT;

    for (int i = tid; i < HH * BT; i += NTHREADS)
        (&h_s[0][0])[i] = 0.0f;
    // stage x transposed: xs_all[t][b] = x[b0+b][t]
    for (int i = tid; i < BT * TT; i += NTHREADS) {
        const int b = i / TT, t = i % TT;
        xs_all[t][b] = x[(b0 + b) * TT + t];
    }

    const float win_j0 = Win[j0], bh_j0 = bh[j0];
    const float win_j1 = Win[j1], bh_j1 = bh[j1];

    // Whh viewed as [512 rows][256 float2]; this thread reads column pair tid.
    const float2* W2 = reinterpret_cast<const float2*>(Whh);

    __syncthreads();

    for (int t = 0; t < TT - 1; ++t) {
        ull acc0[BT / 2], acc1[BT / 2];
        #pragma unroll
        for (int i = 0; i < BT / 2; ++i) { acc0[i] = 0ull; acc1[i] = 0ull; }

        // software pipeline over 64 blocks of 8 k-rows, double-buffered weights
        float2 wbA[8], wbB[8];
        #pragma unroll
        for (int i = 0; i < 8; ++i) wbA[i] = W2[i * (HH / 2) + tid];   // blk 0

        #pragma unroll 1
        for (int blk = 0; blk < 64; blk += 2) {
            const int nb1 = blk + 1;                       // in range (<= 63)
            #pragma unroll
            for (int i = 0; i < 8; ++i) wbB[i] = W2[(nb1 * 8 + i) * (HH / 2) + tid];
            compute_block(wbA, h_s, blk, acc0, acc1);

            const int nb2 = (blk + 2) & 63;                // wrap: L2-hit re-read
            #pragma unroll
            for (int i = 0; i < 8; ++i) wbA[i] = W2[(nb2 * 8 + i) * (HH / 2) + tid];
            compute_block(wbB, h_s, blk + 1, acc0, acc1);
        }

        __syncthreads();   // all h reads done before overwrite

        // epilogue: bit-exact elementwise; vectorized STS.128 writes
        {
            const float* xsrow = &xs_all[t][0];
            float hv[BT];
            #pragma unroll
            for (int i = 0; i < BT / 2; ++i) {
                float alo, ahi; unpack2(alo, ahi, acc0[i]);
                float s0 = __fadd_rn(fmaf(xsrow[2 * i + 0], win_j0, alo), bh_j0);
                float s1 = __fadd_rn(fmaf(xsrow[2 * i + 1], win_j0, ahi), bh_j0);
                hv[2 * i + 0] = tanh_xla_fma(s0);
                hv[2 * i + 1] = tanh_xla_fma(s1);
            }
            float4* dst0 = reinterpret_cast<float4*>(&h_s[j0][0]);
            dst0[0] = make_float4(hv[0],  hv[1],  hv[2],  hv[3]);
            dst0[1] = make_float4(hv[4],  hv[5],  hv[6],  hv[7]);
            dst0[2] = make_float4(hv[8],  hv[9],  hv[10], hv[11]);
            dst0[3] = make_float4(hv[12], hv[13], hv[14], hv[15]);

            #pragma unroll
            for (int i = 0; i < BT / 2; ++i) {
                float alo, ahi; unpack2(alo, ahi, acc1[i]);
                float s0 = __fadd_rn(fmaf(xsrow[2 * i + 0], win_j1, alo), bh_j1);
                float s1 = __fadd_rn(fmaf(xsrow[2 * i + 1], win_j1, ahi), bh_j1);
                hv[2 * i + 0] = tanh_xla_fma(s0);
                hv[2 * i + 1] = tanh_xla_fma(s1);
            }
            float4* dst1 = reinterpret_cast<float4*>(&h_s[j1][0]);
            dst1[0] = make_float4(hv[0],  hv[1],  hv[2],  hv[3]);
            dst1[1] = make_float4(hv[4],  hv[5],  hv[6],  hv[7]);
            dst1[2] = make_float4(hv[8],  hv[9],  hv[10], hv[11]);
            dst1[3] = make_float4(hv[12], hv[13], hv[14], hv[15]);
        }
        __syncthreads();   // h writes visible before next step's reads
    }

    // out[b][c] = (sum_j h[b][j]*Wout[j][c]) + bout[c], chain ascending j (frozen)
    if (tid < BT * CC) {
        const int b = tid / CC;
        const int c = tid % CC;
        float s = 0.0f;
        #pragma unroll 8
        for (int jj = 0; jj < HH; ++jj)
            s = fmaf(h_s[jj][b], Wout[jj * CC + c], s);
        out[(b0 + b) * CC + c] = __fadd_rn(s, bout[c]);
    }
}

extern "C" void kernel_launch(void* const* d_in, const int* in_sizes, int n_in,
                              void* d_out, int out_size)
{
    // dict order: x, Win, Whh, bh, Wout, bout; defensive remap if alphabetical.
    int ix = 0, iwin = 1, iwhh = 2, ibh = 3, iwout = 4, ibout = 5;
    if (n_in == 6 && in_sizes[2] == 5120) {
        iwhh = 0; iwin = 1; iwout = 2; ibh = 3; ibout = 4; ix = 5;
    }

    const float* x    = (const float*)d_in[ix];
    const float* Win  = (const float*)d_in[iwin];
    const float* Whh  = (const float*)d_in[iwhh];
    const float* bh   = (const float*)d_in[ibh];
    const float* Wout = (const float*)d_in[iwout];
    const float* bout = (const float*)d_in[ibout];
    float* out = (float*)d_out;

    dim3 grid(BB / BT);      // 128 CTAs -> 1 CTA/SM
    dim3 block(NTHREADS);    // 256 threads, 2 adjacent hidden columns each
    vanilla_rnn_kernel<<<grid, block>>>(x, Win, Whh, bh, Wout, bout, out);
}